// round 2
// baseline (speedup 1.0000x reference)
#include <cuda_runtime.h>
#include <cuda_bf16.h>

#define L_SEQ 3072
#define D_MODEL 512
#define N_TOKENS 3071

// ---------------- scratch (allocation-free: __device__ globals) ----------------
__device__ float g_X [L_SEQ * D_MODEL];
__device__ float g_X2[L_SEQ * D_MODEL];
__device__ float g_Q [L_SEQ * D_MODEL];
__device__ float g_K [L_SEQ * D_MODEL];
__device__ float g_V [L_SEQ * D_MODEL];
__device__ float g_O [L_SEQ * D_MODEL];
__device__ float g_A [L_SEQ * D_MODEL];
__device__ float g_XA[L_SEQ * D_MODEL];
__device__ float g_H1[L_SEQ * D_MODEL];
__device__ float g_Y [L_SEQ * D_MODEL];
__device__ int   g_SEG[L_SEQ];

// ---------------- embedding: x[0]=sos, x[n]=Wt[:,t]+bt+Wa[:,a]+ba+Wm[:,m]+bm ---
__global__ void embed_kernel(const int* __restrict__ idx,
                             const float* __restrict__ Wt, const float* __restrict__ bt,
                             const float* __restrict__ Wa, const float* __restrict__ ba,
                             const float* __restrict__ Wm, const float* __restrict__ bm,
                             const float* __restrict__ sos,
                             float* __restrict__ X)
{
    int n = blockIdx.x;
    int d = threadIdx.x;             // 512 threads
    if (n == 0) { X[d] = sos[d]; return; }
    int id = idx[n - 1];
    int t  = id / 219;               // N_ARGS*N_MAPS = 73*3
    int a  = (id / 3) % 73;
    int m  = id % 3;
    float r = bt[d] + ba[d] + bm[d];
    r += Wt[d * 15 + t];
    r += Wa[d * 73 + a];
    r += Wm[d * 3  + m];
    X[n * D_MODEL + d] = r;
}

// ---------------- segment-start scan (mask structure) --------------------------
// bid[i] (i>=1) = cumsum(seq_masks==0)[i-1]; bid monotone => allowed keys for
// row i are {0} U [seg_start[i], i-1]. seg boundary at i iff i==1 or seq_masks[i-1]==0.
__global__ void seg_kernel(const int* __restrict__ seq_masks, int* __restrict__ seg)
{
    __shared__ int sm[N_TOKENS];
    __shared__ int ss[L_SEQ];
    for (int i = threadIdx.x; i < N_TOKENS; i += blockDim.x) sm[i] = seq_masks[i];
    __syncthreads();
    if (threadIdx.x == 0) {
        ss[0] = 0;
        int cur = 1;
        ss[1] = 1;
        for (int i = 2; i < L_SEQ; i++) {
            if (sm[i - 1] == 0) cur = i;
            ss[i] = cur;
        }
    }
    __syncthreads();
    for (int i = threadIdx.x; i < L_SEQ; i += blockDim.x) seg[i] = ss[i];
}

// ---------------- SGEMM: C[M,N] = A[M,K] @ B[N,K]^T + bias, optional leaky-relu -
// 64x64 block tile, 16 K-tile, 256 threads, 4x4 microtile, float4 everywhere.
__global__ void __launch_bounds__(256)
gemm_bias(const float* __restrict__ A, const float* __restrict__ B,
          const float* __restrict__ bias, float* __restrict__ C,
          int M, int N, int K, int act)
{
    __shared__ float As[16][64];
    __shared__ float Bs[16][64];
    const int tid  = threadIdx.x;
    const int tx   = tid & 15;
    const int ty   = tid >> 4;
    const int lrow = tid >> 2;        // 0..63
    const int lk   = (tid & 3) << 2;  // 0,4,8,12

    const float* Ap = A + (blockIdx.y * 64 + lrow) * K + lk;
    const float* Bp = B + (blockIdx.x * 64 + lrow) * K + lk;

    float acc[4][4] = {};

    for (int k0 = 0; k0 < K; k0 += 16) {
        float4 av = *(const float4*)(Ap + k0);
        float4 bv = *(const float4*)(Bp + k0);
        __syncthreads();
        As[lk + 0][lrow] = av.x; As[lk + 1][lrow] = av.y;
        As[lk + 2][lrow] = av.z; As[lk + 3][lrow] = av.w;
        Bs[lk + 0][lrow] = bv.x; Bs[lk + 1][lrow] = bv.y;
        Bs[lk + 2][lrow] = bv.z; Bs[lk + 3][lrow] = bv.w;
        __syncthreads();
#pragma unroll
        for (int kk = 0; kk < 16; kk++) {
            float4 a = *(const float4*)(As[kk] + (ty << 2));
            float4 b = *(const float4*)(Bs[kk] + (tx << 2));
            acc[0][0] += a.x * b.x; acc[0][1] += a.x * b.y; acc[0][2] += a.x * b.z; acc[0][3] += a.x * b.w;
            acc[1][0] += a.y * b.x; acc[1][1] += a.y * b.y; acc[1][2] += a.y * b.z; acc[1][3] += a.y * b.w;
            acc[2][0] += a.z * b.x; acc[2][1] += a.z * b.y; acc[2][2] += a.z * b.z; acc[2][3] += a.z * b.w;
            acc[3][0] += a.w * b.x; acc[3][1] += a.w * b.y; acc[3][2] += a.w * b.z; acc[3][3] += a.w * b.w;
        }
    }

    const int row = blockIdx.y * 64 + (ty << 2);
    const int col = blockIdx.x * 64 + (tx << 2);
    float4 bz = *(const float4*)(bias + col);
#pragma unroll
    for (int i = 0; i < 4; i++) {
        float4 o;
        o.x = acc[i][0] + bz.x;
        o.y = acc[i][1] + bz.y;
        o.z = acc[i][2] + bz.z;
        o.w = acc[i][3] + bz.w;
        if (act) {  // leaky_relu, slope 0.01
            o.x = o.x > 0.f ? o.x : 0.01f * o.x;
            o.y = o.y > 0.f ? o.y : 0.01f * o.y;
            o.z = o.z > 0.f ? o.z : 0.01f * o.z;
            o.w = o.w > 0.f ? o.w : 0.01f * o.w;
        }
        *(float4*)(C + (row + i) * N + col) = o;
    }
}

// ---------------- segment-sparse attention, warp per (query, head) -------------
// For row i: keys are j=0 plus j in [seg_start[i], i-1]. Online softmax.
__global__ void __launch_bounds__(256)
attn_kernel(const float* __restrict__ Q, const float* __restrict__ K,
            const float* __restrict__ V, const int* __restrict__ seg,
            float* __restrict__ O)
{
    const int i    = blockIdx.x;
    const int h    = threadIdx.x >> 5;   // 8 warps = 8 heads
    const int lane = threadIdx.x & 31;
    const int base = (h << 6) + (lane << 1);   // h*64 + lane*2

    float2 q = *(const float2*)(Q + i * D_MODEL + base);
    q.x *= 0.125f;  // 1/sqrt(64)
    q.y *= 0.125f;

    float m = -1e30f, l = 0.f, a0 = 0.f, a1 = 0.f;
    const int s = seg[i];

    // j = 0, then j = s..i-1 (s >= 1 for i >= 1, so no double count)
    int j = 0;
    bool first = true;
    for (;;) {
        float2 kv = *(const float2*)(K + j * D_MODEL + base);
        float p = q.x * kv.x + q.y * kv.y;
#pragma unroll
        for (int o = 16; o; o >>= 1) p += __shfl_xor_sync(0xffffffffu, p, o);
        float sc   = p;
        float mnew = fmaxf(m, sc);
        float corr = __expf(m - mnew);
        float pe   = __expf(sc - mnew);
        float2 vv = *(const float2*)(V + j * D_MODEL + base);
        l  = l  * corr + pe;
        a0 = a0 * corr + pe * vv.x;
        a1 = a1 * corr + pe * vv.y;
        m = mnew;
        if (first) { first = false; j = s; } else { j++; }
        if (j >= i) break;
    }

    float inv = 1.f / l;
    float2 o;
    o.x = a0 * inv;
    o.y = a1 * inv;
    *(float2*)(O + i * D_MODEL + base) = o;
}

// ---------------- LayerNorm (optional residual add) ----------------------------
__global__ void __launch_bounds__(256)
ln_kernel(const float* __restrict__ X, const float* __restrict__ R,
          const float* __restrict__ g, const float* __restrict__ b,
          float* __restrict__ Out)
{
    const int row = blockIdx.x;
    const int t   = threadIdx.x;     // 256 threads x float2 = 512
    float2 v = *(const float2*)(X + row * D_MODEL + (t << 1));
    if (R) {
        float2 r = *(const float2*)(R + row * D_MODEL + (t << 1));
        v.x += r.x; v.y += r.y;
    }
    float s  = v.x + v.y;
    float sq = v.x * v.x + v.y * v.y;
#pragma unroll
    for (int o = 16; o; o >>= 1) {
        s  += __shfl_xor_sync(0xffffffffu, s,  o);
        sq += __shfl_xor_sync(0xffffffffu, sq, o);
    }
    __shared__ float ss[8], sqs[8];
    const int warp = t >> 5, lane = t & 31;
    if (lane == 0) { ss[warp] = s; sqs[warp] = sq; }
    __syncthreads();
    if (warp == 0) {
        float a = (lane < 8) ? ss[lane]  : 0.f;
        float c = (lane < 8) ? sqs[lane] : 0.f;
#pragma unroll
        for (int o = 4; o; o >>= 1) {
            a += __shfl_xor_sync(0xffffffffu, a, o);
            c += __shfl_xor_sync(0xffffffffu, c, o);
        }
        if (lane == 0) { ss[0] = a; sqs[0] = c; }
    }
    __syncthreads();
    const float mu  = ss[0]  * (1.f / 512.f);
    const float var = sqs[0] * (1.f / 512.f) - mu * mu;
    const float inv = rsqrtf(var + 1e-5f);
    float2 gg = *(const float2*)(g + (t << 1));
    float2 bb = *(const float2*)(b + (t << 1));
    float2 o;
    o.x = (v.x - mu) * inv * gg.x + bb.x;
    o.y = (v.y - mu) * inv * gg.y + bb.y;
    *(float2*)(Out + row * D_MODEL + (t << 1)) = o;
}

// ---------------- host orchestration -------------------------------------------
static void run_layer(const float* xin, float* xout,
                      const float* Wq, const float* bq, const float* Wk, const float* bk,
                      const float* Wv, const float* bv, const float* Wo, const float* bo,
                      const float* W1, const float* b1, const float* W2, const float* b2,
                      const float* g1, const float* be1, const float* g2, const float* be2,
                      float* pQ, float* pK, float* pV, float* pO, float* pA,
                      float* pXA, float* pH1, float* pY, int* pSeg)
{
    dim3 grid(D_MODEL / 64, L_SEQ / 64);   // (8, 48)
    gemm_bias<<<grid, 256>>>(xin, Wq, bq, pQ, L_SEQ, D_MODEL, D_MODEL, 0);
    gemm_bias<<<grid, 256>>>(xin, Wk, bk, pK, L_SEQ, D_MODEL, D_MODEL, 0);
    gemm_bias<<<grid, 256>>>(xin, Wv, bv, pV, L_SEQ, D_MODEL, D_MODEL, 0);
    attn_kernel<<<L_SEQ, 256>>>(pQ, pK, pV, pSeg, pO);
    gemm_bias<<<grid, 256>>>(pO, Wo, bo, pA, L_SEQ, D_MODEL, D_MODEL, 0);
    ln_kernel<<<L_SEQ, 256>>>(pA, nullptr, g1, be1, pXA);
    gemm_bias<<<grid, 256>>>(pXA, W1, b1, pH1, L_SEQ, D_MODEL, D_MODEL, 1);  // leaky relu
    gemm_bias<<<grid, 256>>>(pH1, W2, b2, pY, L_SEQ, D_MODEL, D_MODEL, 0);
    ln_kernel<<<L_SEQ, 256>>>(pY, pXA, g2, be2, xout);
}

extern "C" void kernel_launch(void* const* d_in, const int* in_sizes, int n_in,
                              void* d_out, int out_size)
{
    const int*   idx  = (const int*)  d_in[0];
    const int*   seqm = (const int*)  d_in[1];
    const float* Wt   = (const float*)d_in[2];
    const float* bt   = (const float*)d_in[3];
    const float* Wa   = (const float*)d_in[4];
    const float* ba   = (const float*)d_in[5];
    const float* Wm   = (const float*)d_in[6];
    const float* bm   = (const float*)d_in[7];
    const float* sos  = (const float*)d_in[8];
    const float* Wq   = (const float*)d_in[9];
    const float* bq   = (const float*)d_in[10];
    const float* Wk   = (const float*)d_in[11];
    const float* bk   = (const float*)d_in[12];
    const float* Wv   = (const float*)d_in[13];
    const float* bv   = (const float*)d_in[14];
    const float* Wo   = (const float*)d_in[15];
    const float* bo   = (const float*)d_in[16];
    const float* W1   = (const float*)d_in[17];
    const float* b1   = (const float*)d_in[18];
    const float* W2   = (const float*)d_in[19];
    const float* b2   = (const float*)d_in[20];
    const float* g1   = (const float*)d_in[21];
    const float* be1  = (const float*)d_in[22];
    const float* g2   = (const float*)d_in[23];
    const float* be2  = (const float*)d_in[24];
    float* out = (float*)d_out;

    float *pX, *pX2, *pQ, *pK, *pV, *pO, *pA, *pXA, *pH1, *pY;
    int* pSeg;
    cudaGetSymbolAddress((void**)&pX,  g_X);
    cudaGetSymbolAddress((void**)&pX2, g_X2);
    cudaGetSymbolAddress((void**)&pQ,  g_Q);
    cudaGetSymbolAddress((void**)&pK,  g_K);
    cudaGetSymbolAddress((void**)&pV,  g_V);
    cudaGetSymbolAddress((void**)&pO,  g_O);
    cudaGetSymbolAddress((void**)&pA,  g_A);
    cudaGetSymbolAddress((void**)&pXA, g_XA);
    cudaGetSymbolAddress((void**)&pH1, g_H1);
    cudaGetSymbolAddress((void**)&pY,  g_Y);
    cudaGetSymbolAddress((void**)&pSeg, g_SEG);

    embed_kernel<<<L_SEQ, D_MODEL>>>(idx, Wt, bt, Wa, ba, Wm, bm, sos, pX);
    seg_kernel<<<1, 256>>>(seqm, pSeg);

    run_layer(pX,  pX2, Wq, bq, Wk, bk, Wv, bv, Wo, bo, W1, b1, W2, b2,
              g1, be1, g2, be2, pQ, pK, pV, pO, pA, pXA, pH1, pY, pSeg);
    run_layer(pX2, out, Wq, bq, Wk, bk, Wv, bv, Wo, bo, W1, b1, W2, b2,
              g1, be1, g2, be2, pQ, pK, pV, pO, pA, pXA, pH1, pY, pSeg);
}

// round 4
// speedup vs baseline: 1.1658x; 1.1658x over previous
#include <cuda_runtime.h>
#include <cuda_bf16.h>
#include <mma.h>
#include <cstdint>

using namespace nvcuda;

#define L_SEQ 3072
#define D_MODEL 512
#define N_TOKENS 3071

// ======================= scratch (allocation-free) =============================
__device__ float g_X [L_SEQ * D_MODEL];
__device__ float g_X2[L_SEQ * D_MODEL];
__device__ float g_Q [L_SEQ * D_MODEL];
__device__ float g_K [L_SEQ * D_MODEL];
__device__ float g_V [L_SEQ * D_MODEL];
__device__ float g_O [L_SEQ * D_MODEL];
__device__ float g_A [L_SEQ * D_MODEL];
__device__ float g_XA[L_SEQ * D_MODEL];
__device__ float g_H1[L_SEQ * D_MODEL];
__device__ float g_Y [L_SEQ * D_MODEL];
__device__ int   g_SEG[L_SEQ];

// bf16 hi/lo split buffers (uint4-typed for 16B alignment)
__device__ uint4 g_AHI[L_SEQ * D_MODEL * 2 / 16];
__device__ uint4 g_ALO[L_SEQ * D_MODEL * 2 / 16];
__device__ uint4 g_WHI[6 * D_MODEL * D_MODEL * 2 / 16];
__device__ uint4 g_WLO[6 * D_MODEL * D_MODEL * 2 / 16];

// ======================= split fp32 -> bf16 hi/lo ==============================
__global__ void __launch_bounds__(256)
split_kernel(const float* __restrict__ src, __nv_bfloat16* __restrict__ hi,
             __nv_bfloat16* __restrict__ lo, int n4)
{
    int i = blockIdx.x * blockDim.x + threadIdx.x;
    if (i >= n4) return;
    float4 v = ((const float4*)src)[i];
    __nv_bfloat16 h0 = __float2bfloat16(v.x);
    __nv_bfloat16 h1 = __float2bfloat16(v.y);
    __nv_bfloat16 h2 = __float2bfloat16(v.z);
    __nv_bfloat16 h3 = __float2bfloat16(v.w);
    __nv_bfloat16 l0 = __float2bfloat16(v.x - __bfloat162float(h0));
    __nv_bfloat16 l1 = __float2bfloat16(v.y - __bfloat162float(h1));
    __nv_bfloat16 l2 = __float2bfloat16(v.z - __bfloat162float(h2));
    __nv_bfloat16 l3 = __float2bfloat16(v.w - __bfloat162float(h3));
    __nv_bfloat162 hA = __nv_bfloat162(h0, h1), hB = __nv_bfloat162(h2, h3);
    __nv_bfloat162 lA = __nv_bfloat162(l0, l1), lB = __nv_bfloat162(l2, l3);
    uint2 uh, ul;
    uh.x = *(uint32_t*)&hA; uh.y = *(uint32_t*)&hB;
    ul.x = *(uint32_t*)&lA; ul.y = *(uint32_t*)&lB;
    ((uint2*)hi)[i] = uh;
    ((uint2*)lo)[i] = ul;
}

// ======================= WMMA bf16x3 GEMM: C = A @ B^T + bias =================
// A: [3072,512] f32 pre-split into Ahi/Alo (K-major). B: [512,512] weights
// pre-split into Bhi/Blo (row-major = K-major for B^T). fp32 accumulate.
// CTA tile 128x128, 8 warps of 32x64 each, K chunks of 32.
struct GemmB { const __nv_bfloat16* bh; const __nv_bfloat16* bl;
               const float* bias; float* c; };
struct GemmB3 { GemmB m[3]; };

#define LDS_K  40                         // 32 + 8 pad, bf16 elems
#define TILE_B (128 * LDS_K * 2)          // 10240 bytes per operand tile
#define GT_SMEM 65536                     // epilogue staging dominates

__global__ void __launch_bounds__(256)
gemm_wmma(const __nv_bfloat16* __restrict__ Ahi, const __nv_bfloat16* __restrict__ Alo,
          GemmB3 P, int act)
{
    extern __shared__ __align__(128) char smem[];
    const GemmB g = P.m[blockIdx.z];
    const int tid  = threadIdx.x;
    const int wid  = tid >> 5;
    const int lane = tid & 31;
    const int rowM0 = blockIdx.y * 128;
    const int colN0 = blockIdx.x * 128;

    // warp tiling: wm in 0..3 (M), wn in 0..1 (N)
    const int wm = wid & 3;
    const int wn = wid >> 2;

    __nv_bfloat16* sAh = (__nv_bfloat16*)(smem);
    __nv_bfloat16* sAl = (__nv_bfloat16*)(smem + TILE_B);
    __nv_bfloat16* sBh = (__nv_bfloat16*)(smem + 2 * TILE_B);
    __nv_bfloat16* sBl = (__nv_bfloat16*)(smem + 3 * TILE_B);

    // loader role: 64 threads per tile
    const int tile = tid >> 6;
    const int idx  = tid & 63;
    const __nv_bfloat16* src;
    __nv_bfloat16* sdst;
    if      (tile == 0) { src = Ahi  + rowM0 * 512; sdst = sAh; }
    else if (tile == 1) { src = Alo  + rowM0 * 512; sdst = sAl; }
    else if (tile == 2) { src = g.bh + colN0 * 512; sdst = sBh; }
    else                { src = g.bl + colN0 * 512; sdst = sBl; }

    wmma::fragment<wmma::accumulator, 16, 16, 16, float> acc[2][4];
#pragma unroll
    for (int mt = 0; mt < 2; ++mt)
#pragma unroll
        for (int nt = 0; nt < 4; ++nt)
            wmma::fill_fragment(acc[mt][nt], 0.0f);

    for (int c = 0; c < 16; ++c) {
        __syncthreads();
        // load 128 rows x 32 bf16 per tile: 512 int4 by 64 threads -> 8 each
#pragma unroll
        for (int i = 0; i < 8; ++i) {
            int linear = i * 64 + idx;        // 0..511
            int r  = linear >> 2;             // row 0..127
            int c4 = linear & 3;              // 16B chunk in row
            uint4 v = *(const uint4*)(src + r * 512 + c * 32 + c4 * 8);
            *(uint4*)(sdst + r * LDS_K + c4 * 8) = v;
        }
        __syncthreads();

#pragma unroll
        for (int k16 = 0; k16 < 2; ++k16) {
            wmma::fragment<wmma::matrix_a, 16, 16, 16, __nv_bfloat16, wmma::row_major> ah[2], al[2];
            wmma::fragment<wmma::matrix_b, 16, 16, 16, __nv_bfloat16, wmma::col_major> bh[4], bl[4];
#pragma unroll
            for (int mt = 0; mt < 2; ++mt) {
                const int ar = wm * 32 + mt * 16;
                wmma::load_matrix_sync(ah[mt], sAh + ar * LDS_K + k16 * 16, LDS_K);
                wmma::load_matrix_sync(al[mt], sAl + ar * LDS_K + k16 * 16, LDS_K);
            }
#pragma unroll
            for (int nt = 0; nt < 4; ++nt) {
                const int bc = wn * 64 + nt * 16;
                wmma::load_matrix_sync(bh[nt], sBh + bc * LDS_K + k16 * 16, LDS_K);
                wmma::load_matrix_sync(bl[nt], sBl + bc * LDS_K + k16 * 16, LDS_K);
            }
#pragma unroll
            for (int mt = 0; mt < 2; ++mt)
#pragma unroll
                for (int nt = 0; nt < 4; ++nt) {
                    wmma::mma_sync(acc[mt][nt], ah[mt], bh[nt], acc[mt][nt]);
                    wmma::mma_sync(acc[mt][nt], ah[mt], bl[nt], acc[mt][nt]);
                    wmma::mma_sync(acc[mt][nt], al[mt], bh[nt], acc[mt][nt]);
                }
        }
    }

    // ---------------- epilogue: per-warp smem staging + bias + act ------------
    __syncthreads();   // operand smem no longer needed by any warp
    float* warpArea = (float*)(smem) + wid * (32 * 64);
#pragma unroll
    for (int mt = 0; mt < 2; ++mt)
#pragma unroll
        for (int nt = 0; nt < 4; ++nt)
            wmma::store_matrix_sync(warpArea + (mt * 16) * 64 + nt * 16,
                                    acc[mt][nt], 64, wmma::mem_row_major);
    __syncwarp();

    const int grow = rowM0 + wm * 32 + lane;
    const int gcol = colN0 + wn * 64;
    float* crow = g.c + grow * 512 + gcol;
    const float* bi = g.bias + gcol;
    const float* srow = warpArea + lane * 64;
#pragma unroll
    for (int j = 0; j < 16; ++j) {
        float4 v  = *(const float4*)(srow + j * 4);
        float4 bz = *(const float4*)(bi + j * 4);
        float4 o;
        o.x = v.x + bz.x;
        o.y = v.y + bz.y;
        o.z = v.z + bz.z;
        o.w = v.w + bz.w;
        if (act) {  // leaky relu
            o.x = o.x > 0.f ? o.x : 0.01f * o.x;
            o.y = o.y > 0.f ? o.y : 0.01f * o.y;
            o.z = o.z > 0.f ? o.z : 0.01f * o.z;
            o.w = o.w > 0.f ? o.w : 0.01f * o.w;
        }
        *(float4*)(crow + j * 4) = o;
    }
}

// ======================= embedding ============================================
__global__ void embed_kernel(const int* __restrict__ idx,
                             const float* __restrict__ Wt, const float* __restrict__ bt,
                             const float* __restrict__ Wa, const float* __restrict__ ba,
                             const float* __restrict__ Wm, const float* __restrict__ bm,
                             const float* __restrict__ sos,
                             float* __restrict__ X)
{
    int n = blockIdx.x;
    int d = threadIdx.x;             // 512 threads
    if (n == 0) { X[d] = sos[d]; return; }
    int id = idx[n - 1];
    int t  = id / 219;               // N_ARGS*N_MAPS = 73*3
    int a  = (id / 3) % 73;
    int m  = id % 3;
    float r = bt[d] + ba[d] + bm[d];
    r += Wt[d * 15 + t];
    r += Wa[d * 73 + a];
    r += Wm[d * 3  + m];
    X[n * D_MODEL + d] = r;
}

// ======================= segment-start parallel max-scan ======================
__global__ void __launch_bounds__(1024)
seg_kernel(const int* __restrict__ seq_masks, int* __restrict__ seg)
{
    __shared__ int bnd[L_SEQ];
    __shared__ int tmax[1024];
    const int t = threadIdx.x;
    int run = 0;
#pragma unroll
    for (int e = 0; e < 3; ++e) {
        int i = t * 3 + e;
        int v;
        if (i == 0)      v = 0;
        else if (i == 1) v = 1;
        else             v = (seq_masks[i - 1] == 0) ? i : 0;
        run = max(run, v);
        bnd[i] = run;
    }
    tmax[t] = run;
    __syncthreads();
    for (int o = 1; o < 1024; o <<= 1) {
        int u = (t >= o) ? tmax[t - o] : 0;
        __syncthreads();
        tmax[t] = max(tmax[t], u);
        __syncthreads();
    }
    int excl = (t == 0) ? 0 : tmax[t - 1];
#pragma unroll
    for (int e = 0; e < 3; ++e) {
        int i = t * 3 + e;
        seg[i] = max(bnd[i], excl);
    }
}

// ======================= segment-sparse attention =============================
__global__ void __launch_bounds__(256)
attn_kernel(const float* __restrict__ Q, const float* __restrict__ K,
            const float* __restrict__ V, const int* __restrict__ seg,
            float* __restrict__ O)
{
    const int i    = blockIdx.x;
    const int h    = threadIdx.x >> 5;
    const int lane = threadIdx.x & 31;
    const int base = (h << 6) + (lane << 1);

    float2 q = *(const float2*)(Q + i * D_MODEL + base);
    q.x *= 0.125f;
    q.y *= 0.125f;

    float m = -1e30f, l = 0.f, a0 = 0.f, a1 = 0.f;
    const int s = seg[i];

    int j = 0;
    bool first = true;
    for (;;) {
        float2 kv = *(const float2*)(K + j * D_MODEL + base);
        float p = q.x * kv.x + q.y * kv.y;
#pragma unroll
        for (int o = 16; o; o >>= 1) p += __shfl_xor_sync(0xffffffffu, p, o);
        float sc   = p;
        float mnew = fmaxf(m, sc);
        float corr = __expf(m - mnew);
        float pe   = __expf(sc - mnew);
        float2 vv = *(const float2*)(V + j * D_MODEL + base);
        l  = l  * corr + pe;
        a0 = a0 * corr + pe * vv.x;
        a1 = a1 * corr + pe * vv.y;
        m = mnew;
        if (first) { first = false; j = s; } else { j++; }
        if (j >= i) break;
    }

    float inv = 1.f / l;
    float2 o;
    o.x = a0 * inv;
    o.y = a1 * inv;
    *(float2*)(O + i * D_MODEL + base) = o;
}

// ======================= LayerNorm (optional residual) ========================
__global__ void __launch_bounds__(256)
ln_kernel(const float* __restrict__ X, const float* __restrict__ R,
          const float* __restrict__ g, const float* __restrict__ b,
          float* __restrict__ Out)
{
    const int row = blockIdx.x;
    const int t   = threadIdx.x;
    float2 v = *(const float2*)(X + row * D_MODEL + (t << 1));
    if (R) {
        float2 r = *(const float2*)(R + row * D_MODEL + (t << 1));
        v.x += r.x; v.y += r.y;
    }
    float s  = v.x + v.y;
    float sq = v.x * v.x + v.y * v.y;
#pragma unroll
    for (int o = 16; o; o >>= 1) {
        s  += __shfl_xor_sync(0xffffffffu, s,  o);
        sq += __shfl_xor_sync(0xffffffffu, sq, o);
    }
    __shared__ float ss[8], sqs[8];
    const int warp = t >> 5, lane = t & 31;
    if (lane == 0) { ss[warp] = s; sqs[warp] = sq; }
    __syncthreads();
    if (warp == 0) {
        float a = (lane < 8) ? ss[lane]  : 0.f;
        float c = (lane < 8) ? sqs[lane] : 0.f;
#pragma unroll
        for (int o = 4; o; o >>= 1) {
            a += __shfl_xor_sync(0xffffffffu, a, o);
            c += __shfl_xor_sync(0xffffffffu, c, o);
        }
        if (lane == 0) { ss[0] = a; sqs[0] = c; }
    }
    __syncthreads();
    const float mu  = ss[0]  * (1.f / 512.f);
    const float var = sqs[0] * (1.f / 512.f) - mu * mu;
    const float inv = rsqrtf(var + 1e-5f);
    float2 gg = *(const float2*)(g + (t << 1));
    float2 bb = *(const float2*)(b + (t << 1));
    float2 o;
    o.x = (v.x - mu) * inv * gg.x + bb.x;
    o.y = (v.y - mu) * inv * gg.y + bb.y;
    *(float2*)(Out + row * D_MODEL + (t << 1)) = o;
}

// ======================= host orchestration ===================================
#define W_ELEMS (D_MODEL * D_MODEL)
#define ACT_N4  (L_SEQ * D_MODEL / 4)
#define W_N4    (W_ELEMS / 4)

extern "C" void kernel_launch(void* const* d_in, const int* in_sizes, int n_in,
                              void* d_out, int out_size)
{
    const int*   idx  = (const int*)  d_in[0];
    const int*   seqm = (const int*)  d_in[1];
    const float* Wt   = (const float*)d_in[2];
    const float* bt   = (const float*)d_in[3];
    const float* Wa   = (const float*)d_in[4];
    const float* ba   = (const float*)d_in[5];
    const float* Wm   = (const float*)d_in[6];
    const float* bm   = (const float*)d_in[7];
    const float* sos  = (const float*)d_in[8];
    const float* Wq   = (const float*)d_in[9];
    const float* bq   = (const float*)d_in[10];
    const float* Wk   = (const float*)d_in[11];
    const float* bk   = (const float*)d_in[12];
    const float* Wv   = (const float*)d_in[13];
    const float* bv   = (const float*)d_in[14];
    const float* Wo   = (const float*)d_in[15];
    const float* bo   = (const float*)d_in[16];
    const float* W1   = (const float*)d_in[17];
    const float* b1   = (const float*)d_in[18];
    const float* W2   = (const float*)d_in[19];
    const float* b2   = (const float*)d_in[20];
    const float* g1   = (const float*)d_in[21];
    const float* be1  = (const float*)d_in[22];
    const float* g2   = (const float*)d_in[23];
    const float* be2  = (const float*)d_in[24];
    float* out = (float*)d_out;

    float *pX, *pX2, *pQ, *pK, *pV, *pO, *pA, *pXA, *pH1, *pY;
    int* pSeg;
    __nv_bfloat16 *pAHI, *pALO, *pWHI, *pWLO;
    cudaGetSymbolAddress((void**)&pX,  g_X);
    cudaGetSymbolAddress((void**)&pX2, g_X2);
    cudaGetSymbolAddress((void**)&pQ,  g_Q);
    cudaGetSymbolAddress((void**)&pK,  g_K);
    cudaGetSymbolAddress((void**)&pV,  g_V);
    cudaGetSymbolAddress((void**)&pO,  g_O);
    cudaGetSymbolAddress((void**)&pA,  g_A);
    cudaGetSymbolAddress((void**)&pXA, g_XA);
    cudaGetSymbolAddress((void**)&pH1, g_H1);
    cudaGetSymbolAddress((void**)&pY,  g_Y);
    cudaGetSymbolAddress((void**)&pSeg, g_SEG);
    cudaGetSymbolAddress((void**)&pAHI, g_AHI);
    cudaGetSymbolAddress((void**)&pALO, g_ALO);
    cudaGetSymbolAddress((void**)&pWHI, g_WHI);
    cudaGetSymbolAddress((void**)&pWLO, g_WLO);

    cudaFuncSetAttribute(gemm_wmma, cudaFuncAttributeMaxDynamicSharedMemorySize, GT_SMEM);

    // weight splits: order q,k,v,o,w1,w2
    const float* Ws[6] = {Wq, Wk, Wv, Wo, W1, W2};
    for (int j = 0; j < 6; ++j)
        split_kernel<<<W_N4 / 256, 256>>>(Ws[j], pWHI + j * W_ELEMS,
                                          pWLO + j * W_ELEMS, W_N4);

    embed_kernel<<<L_SEQ, D_MODEL>>>(idx, Wt, bt, Wa, ba, Wm, bm, sos, pX);
    seg_kernel<<<1, 1024>>>(seqm, pSeg);

    const __nv_bfloat16* wh[6]; const __nv_bfloat16* wl[6];
    for (int j = 0; j < 6; ++j) { wh[j] = pWHI + j * W_ELEMS; wl[j] = pWLO + j * W_ELEMS; }

    dim3 ggrid1(4, 24, 1), ggrid3(4, 24, 3);
    const float* xin = pX;
    float* xout = pX2;

    for (int layer = 0; layer < 2; ++layer) {
        // QKV (batched via blockIdx.z)
        split_kernel<<<ACT_N4 / 256, 256>>>(xin, pAHI, pALO, ACT_N4);
        {
            GemmB3 P;
            P.m[0] = {wh[0], wl[0], bq, pQ};
            P.m[1] = {wh[1], wl[1], bk, pK};
            P.m[2] = {wh[2], wl[2], bv, pV};
            gemm_wmma<<<ggrid3, 256, GT_SMEM>>>(pAHI, pALO, P, 0);
        }
        attn_kernel<<<L_SEQ, 256>>>(pQ, pK, pV, pSeg, pO);
        // Wo
        split_kernel<<<ACT_N4 / 256, 256>>>(pO, pAHI, pALO, ACT_N4);
        {
            GemmB3 P; P.m[0] = {wh[3], wl[3], bo, pA}; P.m[1] = P.m[0]; P.m[2] = P.m[0];
            gemm_wmma<<<ggrid1, 256, GT_SMEM>>>(pAHI, pALO, P, 0);
        }
        ln_kernel<<<L_SEQ, 256>>>(pA, nullptr, g1, be1, pXA);
        // FF1 (leaky relu)
        split_kernel<<<ACT_N4 / 256, 256>>>(pXA, pAHI, pALO, ACT_N4);
        {
            GemmB3 P; P.m[0] = {wh[4], wl[4], b1, pH1}; P.m[1] = P.m[0]; P.m[2] = P.m[0];
            gemm_wmma<<<ggrid1, 256, GT_SMEM>>>(pAHI, pALO, P, 1);
        }
        // FF2
        split_kernel<<<ACT_N4 / 256, 256>>>(pH1, pAHI, pALO, ACT_N4);
        {
            GemmB3 P; P.m[0] = {wh[5], wl[5], b2, pY}; P.m[1] = P.m[0]; P.m[2] = P.m[0];
            gemm_wmma<<<ggrid1, 256, GT_SMEM>>>(pAHI, pALO, P, 0);
        }
        ln_kernel<<<L_SEQ, 256>>>(pY, pXA, g2, be2, xout);

        xin = pX2;
        xout = out;
    }
}

// round 9
// speedup vs baseline: 1.7565x; 1.5067x over previous
#include <cuda_runtime.h>
#include <cuda_bf16.h>
#include <mma.h>
#include <cstdint>

using namespace nvcuda;

#define L_SEQ 3072
#define D_MODEL 512
#define N_TOKENS 3071

// ======================= scratch (allocation-free) =============================
__device__ float g_Q [L_SEQ * D_MODEL];
__device__ float g_K [L_SEQ * D_MODEL];
__device__ float g_V [L_SEQ * D_MODEL];
__device__ float g_A [L_SEQ * D_MODEL];
__device__ float g_XA[L_SEQ * D_MODEL];
__device__ float g_Y [L_SEQ * D_MODEL];
__device__ float g_X2[L_SEQ * D_MODEL];
__device__ int   g_SEG[L_SEQ];

// activation hi/lo pairs (two ping-pong pairs), 16B-aligned
__device__ uint4 g_AH1[L_SEQ * D_MODEL * 2 / 16];
__device__ uint4 g_AL1[L_SEQ * D_MODEL * 2 / 16];
__device__ uint4 g_AH2[L_SEQ * D_MODEL * 2 / 16];
__device__ uint4 g_AL2[L_SEQ * D_MODEL * 2 / 16];
__device__ uint4 g_WHI[6 * D_MODEL * D_MODEL * 2 / 16];
__device__ uint4 g_WLO[6 * D_MODEL * D_MODEL * 2 / 16];

// ======================= split fp32 -> bf16 hi/lo (weights only) ==============
__global__ void __launch_bounds__(256)
split_kernel(const float* __restrict__ src, __nv_bfloat16* __restrict__ hi,
             __nv_bfloat16* __restrict__ lo, int n4)
{
    int i = blockIdx.x * blockDim.x + threadIdx.x;
    if (i >= n4) return;
    float4 v = ((const float4*)src)[i];
    __nv_bfloat16 h0 = __float2bfloat16(v.x);
    __nv_bfloat16 h1 = __float2bfloat16(v.y);
    __nv_bfloat16 h2 = __float2bfloat16(v.z);
    __nv_bfloat16 h3 = __float2bfloat16(v.w);
    __nv_bfloat16 l0 = __float2bfloat16(v.x - __bfloat162float(h0));
    __nv_bfloat16 l1 = __float2bfloat16(v.y - __bfloat162float(h1));
    __nv_bfloat16 l2 = __float2bfloat16(v.z - __bfloat162float(h2));
    __nv_bfloat16 l3 = __float2bfloat16(v.w - __bfloat162float(h3));
    __nv_bfloat162 hA = __nv_bfloat162(h0, h1), hB = __nv_bfloat162(h2, h3);
    __nv_bfloat162 lA = __nv_bfloat162(l0, l1), lB = __nv_bfloat162(l2, l3);
    uint2 uh, ul;
    uh.x = *(uint32_t*)&hA; uh.y = *(uint32_t*)&hB;
    ul.x = *(uint32_t*)&lA; ul.y = *(uint32_t*)&lB;
    ((uint2*)hi)[i] = uh;
    ((uint2*)lo)[i] = ul;
}

// ======================= WMMA bf16x3 pipelined GEMM ===========================
// C[M,N] = A[M,512] @ B[N,512]^T + bias ; A,B pre-split hi/lo bf16 K-major.
// CTA tile 128x64, K chunks of 64, cp.async double buffer, 8 warps of 32x32.
struct GemmOut { const __nv_bfloat16* bh; const __nv_bfloat16* bl;
                 const float* bias; float* cF;
                 __nv_bfloat16* cHi; __nv_bfloat16* cLo; };
struct GemmOut3 { GemmOut m[3]; };

#define CH    64
#define LDSK  72
#define SM_AH 0
#define SM_AL (128 * LDSK)
#define SM_BH (2 * 128 * LDSK)
#define SM_BL (2 * 128 * LDSK + 64 * LDSK)
#define BUF_ELEMS (2 * 128 * LDSK + 2 * 64 * LDSK)   // 27648 bf16
#define GT_SMEM (2 * BUF_ELEMS * 2)                   // 110592 B

__device__ __forceinline__ uint32_t smem_u32(const void* p) {
    uint32_t a;
    asm("{ .reg .u64 t; cvta.to.shared.u64 t, %1; cvt.u32.u64 %0, t; }" : "=r"(a) : "l"(p));
    return a;
}
__device__ __forceinline__ void cp16(uint32_t sdst, const void* gsrc) {
    asm volatile("cp.async.cg.shared.global [%0], [%1], 16;" :: "r"(sdst), "l"(gsrc));
}

__global__ void __launch_bounds__(256, 2)
gemm_wmma(const __nv_bfloat16* __restrict__ Ahi, const __nv_bfloat16* __restrict__ Alo,
          GemmOut3 P, int act)
{
    extern __shared__ __align__(128) __nv_bfloat16 smem[];
    const GemmOut g = P.m[blockIdx.z];
    const uint32_t sb = smem_u32(smem);
    const int tid  = threadIdx.x;
    const int wid  = tid >> 5;
    const int lane = tid & 31;
    const int rowM0 = blockIdx.y * 128;
    const int colN0 = blockIdx.x * 64;
    const int wm = wid & 3;        // 4 M-warps
    const int wn = wid >> 2;       // 2 N-warps

    const __nv_bfloat16* gAh = Ahi  + rowM0 * 512;
    const __nv_bfloat16* gAl = Alo  + rowM0 * 512;
    const __nv_bfloat16* gBh = g.bh + colN0 * 512;
    const __nv_bfloat16* gBl = g.bl + colN0 * 512;

    // per-thread load indices: A 1024 16B-chunks (4/thread each hi,lo), B 512 (2/thread)
    const int ar[4] = { (tid + 0*256) >> 3, (tid + 1*256) >> 3, (tid + 2*256) >> 3, (tid + 3*256) >> 3 };
    const int ac    = (tid & 7) * 8;
    const int br[2] = { (tid + 0*256) >> 3, (tid + 1*256) >> 3 };

#define ISSUE(cc, buf) do {                                                     \
        const int koff = (cc) * CH;                                             \
        const uint32_t bb = sb + (uint32_t)(buf) * (BUF_ELEMS * 2);             \
        _Pragma("unroll")                                                       \
        for (int i = 0; i < 4; ++i) {                                           \
            cp16(bb + (SM_AH + ar[i] * LDSK + ac) * 2, gAh + ar[i] * 512 + koff + ac); \
            cp16(bb + (SM_AL + ar[i] * LDSK + ac) * 2, gAl + ar[i] * 512 + koff + ac); \
        }                                                                       \
        _Pragma("unroll")                                                       \
        for (int i = 0; i < 2; ++i) {                                           \
            cp16(bb + (SM_BH + br[i] * LDSK + ac) * 2, gBh + br[i] * 512 + koff + ac); \
            cp16(bb + (SM_BL + br[i] * LDSK + ac) * 2, gBl + br[i] * 512 + koff + ac); \
        }                                                                       \
        asm volatile("cp.async.commit_group;");                                 \
    } while (0)

    wmma::fragment<wmma::accumulator, 16, 16, 16, float> acc[2][2];
#pragma unroll
    for (int mt = 0; mt < 2; ++mt)
#pragma unroll
        for (int nt = 0; nt < 2; ++nt)
            wmma::fill_fragment(acc[mt][nt], 0.0f);

    ISSUE(0, 0);

    for (int c = 0; c < 8; ++c) {
        if (c < 7) {
            ISSUE(c + 1, (c + 1) & 1);
            asm volatile("cp.async.wait_group 1;");
        } else {
            asm volatile("cp.async.wait_group 0;");
        }
        __syncthreads();

        const __nv_bfloat16* sAh = smem + (c & 1) * BUF_ELEMS + SM_AH;
        const __nv_bfloat16* sAl = smem + (c & 1) * BUF_ELEMS + SM_AL;
        const __nv_bfloat16* sBh = smem + (c & 1) * BUF_ELEMS + SM_BH;
        const __nv_bfloat16* sBl = smem + (c & 1) * BUF_ELEMS + SM_BL;

#pragma unroll
        for (int k16 = 0; k16 < 4; ++k16) {
            wmma::fragment<wmma::matrix_a, 16, 16, 16, __nv_bfloat16, wmma::row_major> ah[2], al[2];
            wmma::fragment<wmma::matrix_b, 16, 16, 16, __nv_bfloat16, wmma::col_major> bh[2], bl[2];
#pragma unroll
            for (int mt = 0; mt < 2; ++mt) {
                const int arow = wm * 32 + mt * 16;
                wmma::load_matrix_sync(ah[mt], sAh + arow * LDSK + k16 * 16, LDSK);
                wmma::load_matrix_sync(al[mt], sAl + arow * LDSK + k16 * 16, LDSK);
            }
#pragma unroll
            for (int nt = 0; nt < 2; ++nt) {
                const int bcol = wn * 32 + nt * 16;
                wmma::load_matrix_sync(bh[nt], sBh + bcol * LDSK + k16 * 16, LDSK);
                wmma::load_matrix_sync(bl[nt], sBl + bcol * LDSK + k16 * 16, LDSK);
            }
#pragma unroll
            for (int mt = 0; mt < 2; ++mt)
#pragma unroll
                for (int nt = 0; nt < 2; ++nt) {
                    wmma::mma_sync(acc[mt][nt], ah[mt], bh[nt], acc[mt][nt]);
                    wmma::mma_sync(acc[mt][nt], ah[mt], bl[nt], acc[mt][nt]);
                    wmma::mma_sync(acc[mt][nt], al[mt], bh[nt], acc[mt][nt]);
                }
        }
        __syncthreads();
    }
#undef ISSUE

    // ---------------- epilogue ------------------------------------------------
    float* warpArea = (float*)smem + wid * (32 * 32);
#pragma unroll
    for (int mt = 0; mt < 2; ++mt)
#pragma unroll
        for (int nt = 0; nt < 2; ++nt)
            wmma::store_matrix_sync(warpArea + mt * 16 * 32 + nt * 16,
                                    acc[mt][nt], 32, wmma::mem_row_major);
    __syncwarp();

    const int grow = rowM0 + wm * 32 + lane;
    const int gcol = colN0 + wn * 32;
    const float* bi = g.bias + gcol;
    const float* srow = warpArea + lane * 32;
#pragma unroll
    for (int j = 0; j < 8; ++j) {
        float4 v  = *(const float4*)(srow + j * 4);
        float4 bz = *(const float4*)(bi + j * 4);
        float4 o;
        o.x = v.x + bz.x; o.y = v.y + bz.y; o.z = v.z + bz.z; o.w = v.w + bz.w;
        if (act) {
            o.x = o.x > 0.f ? o.x : 0.01f * o.x;
            o.y = o.y > 0.f ? o.y : 0.01f * o.y;
            o.z = o.z > 0.f ? o.z : 0.01f * o.z;
            o.w = o.w > 0.f ? o.w : 0.01f * o.w;
        }
        if (g.cF) *(float4*)(g.cF + grow * 512 + gcol + j * 4) = o;
        if (g.cHi) {
            __nv_bfloat16 h0 = __float2bfloat16(o.x), h1 = __float2bfloat16(o.y);
            __nv_bfloat16 h2 = __float2bfloat16(o.z), h3 = __float2bfloat16(o.w);
            __nv_bfloat16 l0 = __float2bfloat16(o.x - __bfloat162float(h0));
            __nv_bfloat16 l1 = __float2bfloat16(o.y - __bfloat162float(h1));
            __nv_bfloat16 l2 = __float2bfloat16(o.z - __bfloat162float(h2));
            __nv_bfloat16 l3 = __float2bfloat16(o.w - __bfloat162float(h3));
            __nv_bfloat162 hA(h0, h1), hB(h2, h3), lA(l0, l1), lB(l2, l3);
            uint2 uh, ul;
            uh.x = *(uint32_t*)&hA; uh.y = *(uint32_t*)&hB;
            ul.x = *(uint32_t*)&lA; ul.y = *(uint32_t*)&lB;
            *(uint2*)(g.cHi + grow * 512 + gcol + j * 4) = uh;
            *(uint2*)(g.cLo + grow * 512 + gcol + j * 4) = ul;
        }
    }
}

// ======================= embedding (emits hi/lo directly) =====================
__global__ void embed_kernel(const int* __restrict__ idx,
                             const float* __restrict__ Wt, const float* __restrict__ bt,
                             const float* __restrict__ Wa, const float* __restrict__ ba,
                             const float* __restrict__ Wm, const float* __restrict__ bm,
                             const float* __restrict__ sos,
                             __nv_bfloat16* __restrict__ XH, __nv_bfloat16* __restrict__ XL)
{
    int n = blockIdx.x;
    int d = threadIdx.x;             // 512 threads
    float r;
    if (n == 0) {
        r = sos[d];
    } else {
        int id = idx[n - 1];
        int t  = id / 219;           // N_ARGS*N_MAPS = 73*3
        int a  = (id / 3) % 73;
        int m  = id % 3;
        r = bt[d] + ba[d] + bm[d];
        r += Wt[d * 15 + t];
        r += Wa[d * 73 + a];
        r += Wm[d * 3  + m];
    }
    __nv_bfloat16 h = __float2bfloat16(r);
    __nv_bfloat16 l = __float2bfloat16(r - __bfloat162float(h));
    XH[n * D_MODEL + d] = h;
    XL[n * D_MODEL + d] = l;
}

// ======================= segment-start parallel max-scan ======================
__global__ void __launch_bounds__(1024)
seg_kernel(const int* __restrict__ seq_masks, int* __restrict__ seg)
{
    __shared__ int bnd[L_SEQ];
    __shared__ int tmax[1024];
    const int t = threadIdx.x;
    int run = 0;
#pragma unroll
    for (int e = 0; e < 3; ++e) {
        int i = t * 3 + e;
        int v;
        if (i == 0)      v = 0;
        else if (i == 1) v = 1;
        else             v = (seq_masks[i - 1] == 0) ? i : 0;
        run = max(run, v);
        bnd[i] = run;
    }
    tmax[t] = run;
    __syncthreads();
    for (int o = 1; o < 1024; o <<= 1) {
        int u = (t >= o) ? tmax[t - o] : 0;
        __syncthreads();
        tmax[t] = max(tmax[t], u);
        __syncthreads();
    }
    int excl = (t == 0) ? 0 : tmax[t - 1];
#pragma unroll
    for (int e = 0; e < 3; ++e) {
        int i = t * 3 + e;
        seg[i] = max(bnd[i], excl);
    }
}

// ======================= segment-sparse attention (emits hi/lo) ===============
__global__ void __launch_bounds__(256)
attn_kernel(const float* __restrict__ Q, const float* __restrict__ K,
            const float* __restrict__ V, const int* __restrict__ seg,
            __nv_bfloat16* __restrict__ OH, __nv_bfloat16* __restrict__ OL)
{
    const int i    = blockIdx.x;
    const int h    = threadIdx.x >> 5;
    const int lane = threadIdx.x & 31;
    const int base = (h << 6) + (lane << 1);

    float2 q = *(const float2*)(Q + i * D_MODEL + base);
    q.x *= 0.125f;
    q.y *= 0.125f;

    float m = -1e30f, l = 0.f, a0 = 0.f, a1 = 0.f;
    const int s = seg[i];

    int j = 0;
    bool first = true;
    for (;;) {
        float2 kv = *(const float2*)(K + j * D_MODEL + base);
        float p = q.x * kv.x + q.y * kv.y;
#pragma unroll
        for (int o = 16; o; o >>= 1) p += __shfl_xor_sync(0xffffffffu, p, o);
        float sc   = p;
        float mnew = fmaxf(m, sc);
        float corr = __expf(m - mnew);
        float pe   = __expf(sc - mnew);
        float2 vv = *(const float2*)(V + j * D_MODEL + base);
        l  = l  * corr + pe;
        a0 = a0 * corr + pe * vv.x;
        a1 = a1 * corr + pe * vv.y;
        m = mnew;
        if (first) { first = false; j = s; } else { j++; }
        if (j >= i) break;
    }

    float inv = 1.f / l;
    float ox = a0 * inv, oy = a1 * inv;
    __nv_bfloat16 h0 = __float2bfloat16(ox), h1 = __float2bfloat16(oy);
    __nv_bfloat16 l0 = __float2bfloat16(ox - __bfloat162float(h0));
    __nv_bfloat16 l1 = __float2bfloat16(oy - __bfloat162float(h1));
    __nv_bfloat162 hv(h0, h1), lv(l0, l1);
    *(__nv_bfloat162*)(OH + i * D_MODEL + base) = hv;
    *(__nv_bfloat162*)(OL + i * D_MODEL + base) = lv;
}

// ======================= LayerNorm (residual opt; f32 + hi/lo outs) ==========
__global__ void __launch_bounds__(256)
ln_kernel(const float* __restrict__ X, const float* __restrict__ R,
          const float* __restrict__ g, const float* __restrict__ b,
          float* __restrict__ OutF,
          __nv_bfloat16* __restrict__ OutH, __nv_bfloat16* __restrict__ OutL)
{
    const int row = blockIdx.x;
    const int t   = threadIdx.x;
    float2 v = *(const float2*)(X + row * D_MODEL + (t << 1));
    if (R) {
        float2 r = *(const float2*)(R + row * D_MODEL + (t << 1));
        v.x += r.x; v.y += r.y;
    }
    float s  = v.x + v.y;
    float sq = v.x * v.x + v.y * v.y;
#pragma unroll
    for (int o = 16; o; o >>= 1) {
        s  += __shfl_xor_sync(0xffffffffu, s,  o);
        sq += __shfl_xor_sync(0xffffffffu, sq, o);
    }
    __shared__ float ss[8], sqs[8];
    const int warp = t >> 5, lane = t & 31;
    if (lane == 0) { ss[warp] = s; sqs[warp] = sq; }
    __syncthreads();
    if (warp == 0) {
        float a = (lane < 8) ? ss[lane]  : 0.f;
        float c = (lane < 8) ? sqs[lane] : 0.f;
#pragma unroll
        for (int o = 4; o; o >>= 1) {
            a += __shfl_xor_sync(0xffffffffu, a, o);
            c += __shfl_xor_sync(0xffffffffu, c, o);
        }
        if (lane == 0) { ss[0] = a; sqs[0] = c; }
    }
    __syncthreads();
    const float mu  = ss[0]  * (1.f / 512.f);
    const float var = sqs[0] * (1.f / 512.f) - mu * mu;
    const float inv = rsqrtf(var + 1e-5f);
    float2 gg = *(const float2*)(g + (t << 1));
    float2 bb = *(const float2*)(b + (t << 1));
    float ox = (v.x - mu) * inv * gg.x + bb.x;
    float oy = (v.y - mu) * inv * gg.y + bb.y;
    if (OutF) {
        float2 o; o.x = ox; o.y = oy;
        *(float2*)(OutF + row * D_MODEL + (t << 1)) = o;
    }
    if (OutH) {
        __nv_bfloat16 h0 = __float2bfloat16(ox), h1 = __float2bfloat16(oy);
        __nv_bfloat16 l0 = __float2bfloat16(ox - __bfloat162float(h0));
        __nv_bfloat16 l1 = __float2bfloat16(oy - __bfloat162float(h1));
        __nv_bfloat162 hv(h0, h1), lv(l0, l1);
        *(__nv_bfloat162*)(OutH + row * D_MODEL + (t << 1)) = hv;
        *(__nv_bfloat162*)(OutL + row * D_MODEL + (t << 1)) = lv;
    }
}

// ======================= host orchestration ===================================
#define W_ELEMS (D_MODEL * D_MODEL)
#define W_N4    (W_ELEMS / 4)

extern "C" void kernel_launch(void* const* d_in, const int* in_sizes, int n_in,
                              void* d_out, int out_size)
{
    const int*   idx  = (const int*)  d_in[0];
    const int*   seqm = (const int*)  d_in[1];
    const float* Wt   = (const float*)d_in[2];
    const float* bt   = (const float*)d_in[3];
    const float* Wa   = (const float*)d_in[4];
    const float* ba   = (const float*)d_in[5];
    const float* Wm   = (const float*)d_in[6];
    const float* bm   = (const float*)d_in[7];
    const float* sos  = (const float*)d_in[8];
    const float* Wq   = (const float*)d_in[9];
    const float* bq   = (const float*)d_in[10];
    const float* Wk   = (const float*)d_in[11];
    const float* bk   = (const float*)d_in[12];
    const float* Wv   = (const float*)d_in[13];
    const float* bv   = (const float*)d_in[14];
    const float* Wo   = (const float*)d_in[15];
    const float* bo   = (const float*)d_in[16];
    const float* W1   = (const float*)d_in[17];
    const float* b1   = (const float*)d_in[18];
    const float* W2   = (const float*)d_in[19];
    const float* b2   = (const float*)d_in[20];
    const float* g1   = (const float*)d_in[21];
    const float* be1  = (const float*)d_in[22];
    const float* g2   = (const float*)d_in[23];
    const float* be2  = (const float*)d_in[24];
    float* out = (float*)d_out;

    float *pQ, *pK, *pV, *pA, *pXA, *pY, *pX2;
    int* pSeg;
    __nv_bfloat16 *pAH1, *pAL1, *pAH2, *pAL2, *pWHI, *pWLO;
    cudaGetSymbolAddress((void**)&pQ,  g_Q);
    cudaGetSymbolAddress((void**)&pK,  g_K);
    cudaGetSymbolAddress((void**)&pV,  g_V);
    cudaGetSymbolAddress((void**)&pA,  g_A);
    cudaGetSymbolAddress((void**)&pXA, g_XA);
    cudaGetSymbolAddress((void**)&pY,  g_Y);
    cudaGetSymbolAddress((void**)&pX2, g_X2);
    cudaGetSymbolAddress((void**)&pSeg, g_SEG);
    cudaGetSymbolAddress((void**)&pAH1, g_AH1);
    cudaGetSymbolAddress((void**)&pAL1, g_AL1);
    cudaGetSymbolAddress((void**)&pAH2, g_AH2);
    cudaGetSymbolAddress((void**)&pAL2, g_AL2);
    cudaGetSymbolAddress((void**)&pWHI, g_WHI);
    cudaGetSymbolAddress((void**)&pWLO, g_WLO);

    cudaFuncSetAttribute(gemm_wmma, cudaFuncAttributeMaxDynamicSharedMemorySize, GT_SMEM);

    // weight splits: order q,k,v,o,w1,w2
    const float* Ws[6] = {Wq, Wk, Wv, Wo, W1, W2};
    for (int j = 0; j < 6; ++j)
        split_kernel<<<W_N4 / 256, 256>>>(Ws[j], pWHI + j * W_ELEMS,
                                          pWLO + j * W_ELEMS, W_N4);

    embed_kernel<<<L_SEQ, D_MODEL>>>(idx, Wt, bt, Wa, ba, Wm, bm, sos, pAH1, pAL1);
    seg_kernel<<<1, 1024>>>(seqm, pSeg);

    const __nv_bfloat16* wh[6]; const __nv_bfloat16* wl[6];
    for (int j = 0; j < 6; ++j) { wh[j] = pWHI + j * W_ELEMS; wl[j] = pWLO + j * W_ELEMS; }

    dim3 grid1(8, 24, 1), grid3(8, 24, 3);

    for (int layer = 0; layer < 2; ++layer) {
        // QKV: pair1 -> f32 Q,K,V
        {
            GemmOut3 P;
            P.m[0] = {wh[0], wl[0], bq, pQ, nullptr, nullptr};
            P.m[1] = {wh[1], wl[1], bk, pK, nullptr, nullptr};
            P.m[2] = {wh[2], wl[2], bv, pV, nullptr, nullptr};
            gemm_wmma<<<grid3, 256, GT_SMEM>>>(pAH1, pAL1, P, 0);
        }
        // attention -> pair2 hi/lo
        attn_kernel<<<L_SEQ, 256>>>(pQ, pK, pV, pSeg, pAH2, pAL2);
        // Wo: pair2 -> f32 A
        {
            GemmOut3 P; P.m[0] = {wh[3], wl[3], bo, pA, nullptr, nullptr};
            P.m[1] = P.m[0]; P.m[2] = P.m[0];
            gemm_wmma<<<grid1, 256, GT_SMEM>>>(pAH2, pAL2, P, 0);
        }
        // ln1: A -> f32 XA + pair1 hi/lo
        ln_kernel<<<L_SEQ, 256>>>(pA, nullptr, g1, be1, pXA, pAH1, pAL1);
        // FF1 (leaky): pair1 -> pair2 hi/lo (no f32)
        {
            GemmOut3 P; P.m[0] = {wh[4], wl[4], b1, nullptr, pAH2, pAL2};
            P.m[1] = P.m[0]; P.m[2] = P.m[0];
            gemm_wmma<<<grid1, 256, GT_SMEM>>>(pAH1, pAL1, P, 1);
        }
        // FF2: pair2 -> f32 Y
        {
            GemmOut3 P; P.m[0] = {wh[5], wl[5], b2, pY, nullptr, nullptr};
            P.m[1] = P.m[0]; P.m[2] = P.m[0];
            gemm_wmma<<<grid1, 256, GT_SMEM>>>(pAH2, pAL2, P, 0);
        }
        // ln2: Y + XA -> f32 (x2 or out) + pair1 hi/lo for next layer QKV
        ln_kernel<<<L_SEQ, 256>>>(pY, pXA, g2, be2,
                                  (layer == 0) ? pX2 : out, pAH1, pAL1);
    }
}

// round 10
// speedup vs baseline: 1.9744x; 1.1241x over previous
#include <cuda_runtime.h>
#include <cuda_bf16.h>
#include <mma.h>
#include <cstdint>

using namespace nvcuda;

#define L_SEQ 3072
#define D_MODEL 512
#define N_TOKENS 3071

// ======================= scratch (allocation-free) =============================
__device__ float g_Q [L_SEQ * D_MODEL];
__device__ float g_K [L_SEQ * D_MODEL];
__device__ float g_V [L_SEQ * D_MODEL];
__device__ float g_A [L_SEQ * D_MODEL];
__device__ float g_XA[L_SEQ * D_MODEL];
__device__ float g_Y [L_SEQ * D_MODEL];
__device__ float g_X2[L_SEQ * D_MODEL];
__device__ int   g_SEG[L_SEQ];

// activation hi/lo pairs (two ping-pong pairs), 16B-aligned
__device__ uint4 g_AH1[L_SEQ * D_MODEL * 2 / 16];
__device__ uint4 g_AL1[L_SEQ * D_MODEL * 2 / 16];
__device__ uint4 g_AH2[L_SEQ * D_MODEL * 2 / 16];
__device__ uint4 g_AL2[L_SEQ * D_MODEL * 2 / 16];
__device__ uint4 g_WHI[6 * D_MODEL * D_MODEL * 2 / 16];
__device__ uint4 g_WLO[6 * D_MODEL * D_MODEL * 2 / 16];

// ======================= fused weight split (all 6 in one launch) =============
struct SplitSrc { const float* s[6]; };

__global__ void __launch_bounds__(256)
split6_kernel(SplitSrc S, __nv_bfloat16* __restrict__ hiBase,
              __nv_bfloat16* __restrict__ loBase, int n4)
{
    const int j = blockIdx.y;
    const float* src = S.s[j];
    __nv_bfloat16* hi = hiBase + j * (D_MODEL * D_MODEL);
    __nv_bfloat16* lo = loBase + j * (D_MODEL * D_MODEL);
    int i = blockIdx.x * blockDim.x + threadIdx.x;
    if (i >= n4) return;
    float4 v = ((const float4*)src)[i];
    __nv_bfloat16 h0 = __float2bfloat16(v.x);
    __nv_bfloat16 h1 = __float2bfloat16(v.y);
    __nv_bfloat16 h2 = __float2bfloat16(v.z);
    __nv_bfloat16 h3 = __float2bfloat16(v.w);
    __nv_bfloat16 l0 = __float2bfloat16(v.x - __bfloat162float(h0));
    __nv_bfloat16 l1 = __float2bfloat16(v.y - __bfloat162float(h1));
    __nv_bfloat16 l2 = __float2bfloat16(v.z - __bfloat162float(h2));
    __nv_bfloat16 l3 = __float2bfloat16(v.w - __bfloat162float(h3));
    __nv_bfloat162 hA(h0, h1), hB(h2, h3), lA(l0, l1), lB(l2, l3);
    uint2 uh, ul;
    uh.x = *(uint32_t*)&hA; uh.y = *(uint32_t*)&hB;
    ul.x = *(uint32_t*)&lA; ul.y = *(uint32_t*)&lB;
    ((uint2*)hi)[i] = uh;
    ((uint2*)lo)[i] = ul;
}

// ======================= WMMA bf16x3 pipelined GEMM ===========================
// C[M,N] = A[M,512] @ B[N,512]^T + bias ; A,B pre-split hi/lo bf16 K-major.
// CTA tile 128x64, K chunks of 64, cp.async double buffer.
// 128 threads = 4 warps; warp tile 32x64 (2x4 fragments) for better LDS reuse.
struct GemmOut { const __nv_bfloat16* bh; const __nv_bfloat16* bl;
                 const float* bias; float* cF;
                 __nv_bfloat16* cHi; __nv_bfloat16* cLo; };
struct GemmOut3 { GemmOut m[3]; };

#define CH    64
#define LDSK  72
#define SM_AH 0
#define SM_AL (128 * LDSK)
#define SM_BH (2 * 128 * LDSK)
#define SM_BL (2 * 128 * LDSK + 64 * LDSK)
#define BUF_ELEMS (2 * 128 * LDSK + 2 * 64 * LDSK)   // 27648 bf16
#define GT_SMEM (2 * BUF_ELEMS * 2)                   // 110592 B

__device__ __forceinline__ uint32_t smem_u32(const void* p) {
    uint32_t a;
    asm("{ .reg .u64 t; cvta.to.shared.u64 t, %1; cvt.u32.u64 %0, t; }" : "=r"(a) : "l"(p));
    return a;
}
__device__ __forceinline__ void cp16(uint32_t sdst, const void* gsrc) {
    asm volatile("cp.async.cg.shared.global [%0], [%1], 16;" :: "r"(sdst), "l"(gsrc));
}

__global__ void __launch_bounds__(128, 2)
gemm_wmma(const __nv_bfloat16* __restrict__ Ahi, const __nv_bfloat16* __restrict__ Alo,
          GemmOut3 P, int act)
{
    extern __shared__ __align__(128) __nv_bfloat16 smem[];
    const GemmOut g = P.m[blockIdx.z];
    const uint32_t sb = smem_u32(smem);
    const int tid  = threadIdx.x;
    const int wid  = tid >> 5;     // 0..3 = M-warp
    const int lane = tid & 31;
    const int rowM0 = blockIdx.y * 128;
    const int colN0 = blockIdx.x * 64;

    const __nv_bfloat16* gAh = Ahi  + rowM0 * 512;
    const __nv_bfloat16* gAl = Alo  + rowM0 * 512;
    const __nv_bfloat16* gBh = g.bh + colN0 * 512;
    const __nv_bfloat16* gBl = g.bl + colN0 * 512;

#define ISSUE(cc, buf) do {                                                          \
        const int koff = (cc) * CH;                                                  \
        const uint32_t bb = sb + (uint32_t)(buf) * (BUF_ELEMS * 2);                  \
        _Pragma("unroll")                                                            \
        for (int i = 0; i < 8; ++i) {                                                \
            int id = tid + i * 128;            /* 0..1023 */                         \
            int r = id >> 3, c8 = (id & 7) * 8;                                      \
            cp16(bb + (SM_AH + r * LDSK + c8) * 2, gAh + r * 512 + koff + c8);       \
            cp16(bb + (SM_AL + r * LDSK + c8) * 2, gAl + r * 512 + koff + c8);       \
        }                                                                            \
        _Pragma("unroll")                                                            \
        for (int i = 0; i < 4; ++i) {                                                \
            int id = tid + i * 128;            /* 0..511 */                          \
            int r = id >> 3, c8 = (id & 7) * 8;                                      \
            cp16(bb + (SM_BH + r * LDSK + c8) * 2, gBh + r * 512 + koff + c8);       \
            cp16(bb + (SM_BL + r * LDSK + c8) * 2, gBl + r * 512 + koff + c8);       \
        }                                                                            \
        asm volatile("cp.async.commit_group;");                                      \
    } while (0)

    wmma::fragment<wmma::accumulator, 16, 16, 16, float> acc[2][4];
#pragma unroll
    for (int mt = 0; mt < 2; ++mt)
#pragma unroll
        for (int nt = 0; nt < 4; ++nt)
            wmma::fill_fragment(acc[mt][nt], 0.0f);

    ISSUE(0, 0);

    for (int c = 0; c < 8; ++c) {
        if (c < 7) {
            ISSUE(c + 1, (c + 1) & 1);
            asm volatile("cp.async.wait_group 1;");
        } else {
            asm volatile("cp.async.wait_group 0;");
        }
        __syncthreads();

        const __nv_bfloat16* sAh = smem + (c & 1) * BUF_ELEMS + SM_AH;
        const __nv_bfloat16* sAl = smem + (c & 1) * BUF_ELEMS + SM_AL;
        const __nv_bfloat16* sBh = smem + (c & 1) * BUF_ELEMS + SM_BH;
        const __nv_bfloat16* sBl = smem + (c & 1) * BUF_ELEMS + SM_BL;

#pragma unroll
        for (int k16 = 0; k16 < 4; ++k16) {
            wmma::fragment<wmma::matrix_a, 16, 16, 16, __nv_bfloat16, wmma::row_major> ah[2], al[2];
            wmma::fragment<wmma::matrix_b, 16, 16, 16, __nv_bfloat16, wmma::col_major> bh[4], bl[4];
#pragma unroll
            for (int mt = 0; mt < 2; ++mt) {
                const int arow = wid * 32 + mt * 16;
                wmma::load_matrix_sync(ah[mt], sAh + arow * LDSK + k16 * 16, LDSK);
                wmma::load_matrix_sync(al[mt], sAl + arow * LDSK + k16 * 16, LDSK);
            }
#pragma unroll
            for (int nt = 0; nt < 4; ++nt) {
                const int bcol = nt * 16;
                wmma::load_matrix_sync(bh[nt], sBh + bcol * LDSK + k16 * 16, LDSK);
                wmma::load_matrix_sync(bl[nt], sBl + bcol * LDSK + k16 * 16, LDSK);
            }
#pragma unroll
            for (int mt = 0; mt < 2; ++mt)
#pragma unroll
                for (int nt = 0; nt < 4; ++nt) {
                    wmma::mma_sync(acc[mt][nt], ah[mt], bh[nt], acc[mt][nt]);
                    wmma::mma_sync(acc[mt][nt], ah[mt], bl[nt], acc[mt][nt]);
                    wmma::mma_sync(acc[mt][nt], al[mt], bh[nt], acc[mt][nt]);
                }
        }
        __syncthreads();
    }
#undef ISSUE

    // ---------------- epilogue: warp stages 32x64 f32 in smem -----------------
    float* warpArea = (float*)smem + wid * (32 * 64);
#pragma unroll
    for (int mt = 0; mt < 2; ++mt)
#pragma unroll
        for (int nt = 0; nt < 4; ++nt)
            wmma::store_matrix_sync(warpArea + mt * 16 * 64 + nt * 16,
                                    acc[mt][nt], 64, wmma::mem_row_major);
    __syncwarp();

    const int grow = rowM0 + wid * 32 + lane;
    const float* bi = g.bias + colN0;
    const float* srow = warpArea + lane * 64;
#pragma unroll
    for (int j = 0; j < 16; ++j) {
        float4 v  = *(const float4*)(srow + j * 4);
        float4 bz = *(const float4*)(bi + j * 4);
        float4 o;
        o.x = v.x + bz.x; o.y = v.y + bz.y; o.z = v.z + bz.z; o.w = v.w + bz.w;
        if (act) {
            o.x = o.x > 0.f ? o.x : 0.01f * o.x;
            o.y = o.y > 0.f ? o.y : 0.01f * o.y;
            o.z = o.z > 0.f ? o.z : 0.01f * o.z;
            o.w = o.w > 0.f ? o.w : 0.01f * o.w;
        }
        if (g.cF) *(float4*)(g.cF + grow * 512 + colN0 + j * 4) = o;
        if (g.cHi) {
            __nv_bfloat16 h0 = __float2bfloat16(o.x), h1 = __float2bfloat16(o.y);
            __nv_bfloat16 h2 = __float2bfloat16(o.z), h3 = __float2bfloat16(o.w);
            __nv_bfloat16 l0 = __float2bfloat16(o.x - __bfloat162float(h0));
            __nv_bfloat16 l1 = __float2bfloat16(o.y - __bfloat162float(h1));
            __nv_bfloat16 l2 = __float2bfloat16(o.z - __bfloat162float(h2));
            __nv_bfloat16 l3 = __float2bfloat16(o.w - __bfloat162float(h3));
            __nv_bfloat162 hA(h0, h1), hB(h2, h3), lA(l0, l1), lB(l2, l3);
            uint2 uh, ul;
            uh.x = *(uint32_t*)&hA; uh.y = *(uint32_t*)&hB;
            ul.x = *(uint32_t*)&lA; ul.y = *(uint32_t*)&lB;
            *(uint2*)(g.cHi + grow * 512 + colN0 + j * 4) = uh;
            *(uint2*)(g.cLo + grow * 512 + colN0 + j * 4) = ul;
        }
    }
}

// ======================= embedding (emits hi/lo directly) =====================
__global__ void embed_kernel(const int* __restrict__ idx,
                             const float* __restrict__ Wt, const float* __restrict__ bt,
                             const float* __restrict__ Wa, const float* __restrict__ ba,
                             const float* __restrict__ Wm, const float* __restrict__ bm,
                             const float* __restrict__ sos,
                             __nv_bfloat16* __restrict__ XH, __nv_bfloat16* __restrict__ XL)
{
    int n = blockIdx.x;
    int d = threadIdx.x;             // 512 threads
    float r;
    if (n == 0) {
        r = sos[d];
    } else {
        int id = idx[n - 1];
        int t  = id / 219;           // N_ARGS*N_MAPS = 73*3
        int a  = (id / 3) % 73;
        int m  = id % 3;
        r = bt[d] + ba[d] + bm[d];
        r += Wt[d * 15 + t];
        r += Wa[d * 73 + a];
        r += Wm[d * 3  + m];
    }
    __nv_bfloat16 h = __float2bfloat16(r);
    __nv_bfloat16 l = __float2bfloat16(r - __bfloat162float(h));
    XH[n * D_MODEL + d] = h;
    XL[n * D_MODEL + d] = l;
}

// ======================= segment-start parallel max-scan ======================
__global__ void __launch_bounds__(1024)
seg_kernel(const int* __restrict__ seq_masks, int* __restrict__ seg)
{
    __shared__ int bnd[L_SEQ];
    __shared__ int tmax[1024];
    const int t = threadIdx.x;
    int run = 0;
#pragma unroll
    for (int e = 0; e < 3; ++e) {
        int i = t * 3 + e;
        int v;
        if (i == 0)      v = 0;
        else if (i == 1) v = 1;
        else             v = (seq_masks[i - 1] == 0) ? i : 0;
        run = max(run, v);
        bnd[i] = run;
    }
    tmax[t] = run;
    __syncthreads();
    for (int o = 1; o < 1024; o <<= 1) {
        int u = (t >= o) ? tmax[t - o] : 0;
        __syncthreads();
        tmax[t] = max(tmax[t], u);
        __syncthreads();
    }
    int excl = (t == 0) ? 0 : tmax[t - 1];
#pragma unroll
    for (int e = 0; e < 3; ++e) {
        int i = t * 3 + e;
        seg[i] = max(bnd[i], excl);
    }
}

// ======================= segment-sparse attention (float4, emits hi/lo) =======
// 128 threads: warp w holds heads 2w, 2w+1; 16 lanes x float4 per head.
__global__ void __launch_bounds__(128)
attn_kernel(const float* __restrict__ Q, const float* __restrict__ K,
            const float* __restrict__ V, const int* __restrict__ seg,
            __nv_bfloat16* __restrict__ OH, __nv_bfloat16* __restrict__ OL)
{
    const int i    = blockIdx.x;
    const int w    = threadIdx.x >> 5;
    const int lane = threadIdx.x & 31;
    const int h    = (w << 1) + (lane >> 4);   // head 0..7
    const int sl   = lane & 15;
    const int base = (h << 6) + (sl << 2);     // h*64 + sl*4

    float4 q = *(const float4*)(Q + i * D_MODEL + base);
    q.x *= 0.125f; q.y *= 0.125f; q.z *= 0.125f; q.w *= 0.125f;

    float m = -1e30f, l = 0.f;
    float a0 = 0.f, a1 = 0.f, a2 = 0.f, a3 = 0.f;
    const int s = seg[i];

    int j = 0;
    bool first = true;
    for (;;) {
        float4 kv = *(const float4*)(K + j * D_MODEL + base);
        float p = q.x * kv.x + q.y * kv.y + q.z * kv.z + q.w * kv.w;
#pragma unroll
        for (int o = 8; o; o >>= 1) p += __shfl_xor_sync(0xffffffffu, p, o);
        float mnew = fmaxf(m, p);
        float corr = __expf(m - mnew);
        float pe   = __expf(p - mnew);
        float4 vv = *(const float4*)(V + j * D_MODEL + base);
        l  = l  * corr + pe;
        a0 = a0 * corr + pe * vv.x;
        a1 = a1 * corr + pe * vv.y;
        a2 = a2 * corr + pe * vv.z;
        a3 = a3 * corr + pe * vv.w;
        m = mnew;
        if (first) { first = false; j = s; } else { j++; }
        if (j >= i) break;
    }

    float inv = 1.f / l;
    float o0 = a0 * inv, o1 = a1 * inv, o2 = a2 * inv, o3 = a3 * inv;
    __nv_bfloat16 h0 = __float2bfloat16(o0), h1 = __float2bfloat16(o1);
    __nv_bfloat16 h2 = __float2bfloat16(o2), h3 = __float2bfloat16(o3);
    __nv_bfloat16 l0 = __float2bfloat16(o0 - __bfloat162float(h0));
    __nv_bfloat16 l1 = __float2bfloat16(o1 - __bfloat162float(h1));
    __nv_bfloat16 l2 = __float2bfloat16(o2 - __bfloat162float(h2));
    __nv_bfloat16 l3 = __float2bfloat16(o3 - __bfloat162float(h3));
    __nv_bfloat162 hA(h0, h1), hB(h2, h3), lA(l0, l1), lB(l2, l3);
    uint2 uh, ul;
    uh.x = *(uint32_t*)&hA; uh.y = *(uint32_t*)&hB;
    ul.x = *(uint32_t*)&lA; ul.y = *(uint32_t*)&lB;
    *(uint2*)(OH + i * D_MODEL + base) = uh;
    *(uint2*)(OL + i * D_MODEL + base) = ul;
}

// ======================= LayerNorm (residual opt; f32 + hi/lo outs) ==========
__global__ void __launch_bounds__(256)
ln_kernel(const float* __restrict__ X, const float* __restrict__ R,
          const float* __restrict__ g, const float* __restrict__ b,
          float* __restrict__ OutF,
          __nv_bfloat16* __restrict__ OutH, __nv_bfloat16* __restrict__ OutL)
{
    const int row = blockIdx.x;
    const int t   = threadIdx.x;
    float2 v = *(const float2*)(X + row * D_MODEL + (t << 1));
    if (R) {
        float2 r = *(const float2*)(R + row * D_MODEL + (t << 1));
        v.x += r.x; v.y += r.y;
    }
    float s  = v.x + v.y;
    float sq = v.x * v.x + v.y * v.y;
#pragma unroll
    for (int o = 16; o; o >>= 1) {
        s  += __shfl_xor_sync(0xffffffffu, s,  o);
        sq += __shfl_xor_sync(0xffffffffu, sq, o);
    }
    __shared__ float ss[8], sqs[8];
    const int warp = t >> 5, lane = t & 31;
    if (lane == 0) { ss[warp] = s; sqs[warp] = sq; }
    __syncthreads();
    if (warp == 0) {
        float a = (lane < 8) ? ss[lane]  : 0.f;
        float c = (lane < 8) ? sqs[lane] : 0.f;
#pragma unroll
        for (int o = 4; o; o >>= 1) {
            a += __shfl_xor_sync(0xffffffffu, a, o);
            c += __shfl_xor_sync(0xffffffffu, c, o);
        }
        if (lane == 0) { ss[0] = a; sqs[0] = c; }
    }
    __syncthreads();
    const float mu  = ss[0]  * (1.f / 512.f);
    const float var = sqs[0] * (1.f / 512.f) - mu * mu;
    const float inv = rsqrtf(var + 1e-5f);
    float2 gg = *(const float2*)(g + (t << 1));
    float2 bb = *(const float2*)(b + (t << 1));
    float ox = (v.x - mu) * inv * gg.x + bb.x;
    float oy = (v.y - mu) * inv * gg.y + bb.y;
    if (OutF) {
        float2 o; o.x = ox; o.y = oy;
        *(float2*)(OutF + row * D_MODEL + (t << 1)) = o;
    }
    if (OutH) {
        __nv_bfloat16 h0 = __float2bfloat16(ox), h1 = __float2bfloat16(oy);
        __nv_bfloat16 l0 = __float2bfloat16(ox - __bfloat162float(h0));
        __nv_bfloat16 l1 = __float2bfloat16(oy - __bfloat162float(h1));
        __nv_bfloat162 hv(h0, h1), lv(l0, l1);
        *(__nv_bfloat162*)(OutH + row * D_MODEL + (t << 1)) = hv;
        *(__nv_bfloat162*)(OutL + row * D_MODEL + (t << 1)) = lv;
    }
}

// ======================= host orchestration ===================================
#define W_ELEMS (D_MODEL * D_MODEL)
#define W_N4    (W_ELEMS / 4)

extern "C" void kernel_launch(void* const* d_in, const int* in_sizes, int n_in,
                              void* d_out, int out_size)
{
    const int*   idx  = (const int*)  d_in[0];
    const int*   seqm = (const int*)  d_in[1];
    const float* Wt   = (const float*)d_in[2];
    const float* bt   = (const float*)d_in[3];
    const float* Wa   = (const float*)d_in[4];
    const float* ba   = (const float*)d_in[5];
    const float* Wm   = (const float*)d_in[6];
    const float* bm   = (const float*)d_in[7];
    const float* sos  = (const float*)d_in[8];
    const float* Wq   = (const float*)d_in[9];
    const float* bq   = (const float*)d_in[10];
    const float* Wk   = (const float*)d_in[11];
    const float* bk   = (const float*)d_in[12];
    const float* Wv   = (const float*)d_in[13];
    const float* bv   = (const float*)d_in[14];
    const float* Wo   = (const float*)d_in[15];
    const float* bo   = (const float*)d_in[16];
    const float* W1   = (const float*)d_in[17];
    const float* b1   = (const float*)d_in[18];
    const float* W2   = (const float*)d_in[19];
    const float* b2   = (const float*)d_in[20];
    const float* g1   = (const float*)d_in[21];
    const float* be1  = (const float*)d_in[22];
    const float* g2   = (const float*)d_in[23];
    const float* be2  = (const float*)d_in[24];
    float* out = (float*)d_out;

    float *pQ, *pK, *pV, *pA, *pXA, *pY, *pX2;
    int* pSeg;
    __nv_bfloat16 *pAH1, *pAL1, *pAH2, *pAL2, *pWHI, *pWLO;
    cudaGetSymbolAddress((void**)&pQ,  g_Q);
    cudaGetSymbolAddress((void**)&pK,  g_K);
    cudaGetSymbolAddress((void**)&pV,  g_V);
    cudaGetSymbolAddress((void**)&pA,  g_A);
    cudaGetSymbolAddress((void**)&pXA, g_XA);
    cudaGetSymbolAddress((void**)&pY,  g_Y);
    cudaGetSymbolAddress((void**)&pX2, g_X2);
    cudaGetSymbolAddress((void**)&pSeg, g_SEG);
    cudaGetSymbolAddress((void**)&pAH1, g_AH1);
    cudaGetSymbolAddress((void**)&pAL1, g_AL1);
    cudaGetSymbolAddress((void**)&pAH2, g_AH2);
    cudaGetSymbolAddress((void**)&pAL2, g_AL2);
    cudaGetSymbolAddress((void**)&pWHI, g_WHI);
    cudaGetSymbolAddress((void**)&pWLO, g_WLO);

    cudaFuncSetAttribute(gemm_wmma, cudaFuncAttributeMaxDynamicSharedMemorySize, GT_SMEM);

    // weight splits: order q,k,v,o,w1,w2 — single fused launch
    {
        SplitSrc S; S.s[0] = Wq; S.s[1] = Wk; S.s[2] = Wv;
        S.s[3] = Wo; S.s[4] = W1; S.s[5] = W2;
        dim3 sg(W_N4 / 256, 6);
        split6_kernel<<<sg, 256>>>(S, pWHI, pWLO, W_N4);
    }

    embed_kernel<<<L_SEQ, D_MODEL>>>(idx, Wt, bt, Wa, ba, Wm, bm, sos, pAH1, pAL1);
    seg_kernel<<<1, 1024>>>(seqm, pSeg);

    const __nv_bfloat16* wh[6]; const __nv_bfloat16* wl[6];
    for (int j = 0; j < 6; ++j) { wh[j] = pWHI + j * W_ELEMS; wl[j] = pWLO + j * W_ELEMS; }

    dim3 grid1(8, 24, 1), grid3(8, 24, 3);

    for (int layer = 0; layer < 2; ++layer) {
        // QKV: pair1 -> f32 Q,K,V
        {
            GemmOut3 P;
            P.m[0] = {wh[0], wl[0], bq, pQ, nullptr, nullptr};
            P.m[1] = {wh[1], wl[1], bk, pK, nullptr, nullptr};
            P.m[2] = {wh[2], wl[2], bv, pV, nullptr, nullptr};
            gemm_wmma<<<grid3, 128, GT_SMEM>>>(pAH1, pAL1, P, 0);
        }
        // attention -> pair2 hi/lo
        attn_kernel<<<L_SEQ, 128>>>(pQ, pK, pV, pSeg, pAH2, pAL2);
        // Wo: pair2 -> f32 A
        {
            GemmOut3 P; P.m[0] = {wh[3], wl[3], bo, pA, nullptr, nullptr};
            P.m[1] = P.m[0]; P.m[2] = P.m[0];
            gemm_wmma<<<grid1, 128, GT_SMEM>>>(pAH2, pAL2, P, 0);
        }
        // ln1: A -> f32 XA + pair1 hi/lo
        ln_kernel<<<L_SEQ, 256>>>(pA, nullptr, g1, be1, pXA, pAH1, pAL1);
        // FF1 (leaky): pair1 -> pair2 hi/lo (no f32)
        {
            GemmOut3 P; P.m[0] = {wh[4], wl[4], b1, nullptr, pAH2, pAL2};
            P.m[1] = P.m[0]; P.m[2] = P.m[0];
            gemm_wmma<<<grid1, 128, GT_SMEM>>>(pAH1, pAL1, P, 1);
        }
        // FF2: pair2 -> f32 Y
        {
            GemmOut3 P; P.m[0] = {wh[5], wl[5], b2, pY, nullptr, nullptr};
            P.m[1] = P.m[0]; P.m[2] = P.m[0];
            gemm_wmma<<<grid1, 128, GT_SMEM>>>(pAH2, pAL2, P, 0);
        }
        // ln2: Y + XA -> f32 (x2 or out) + pair1 hi/lo for next layer QKV
        ln_kernel<<<L_SEQ, 256>>>(pY, pXA, g2, be2,
                                  (layer == 0) ? pX2 : out, pAH1, pAL1);
    }
}